// round 2
// baseline (speedup 1.0000x reference)
#include <cuda_runtime.h>

#define N_FFT   1024
#define HALF    512
#define NBINS   513
#define NB      64
#define NFRAMES 512
#define HOP     256
#define OUT_PER_B 130816           // 511*256
#define TOTAL_FRAMES (NB * NFRAMES)

// Scratch: windowed irfft frames, stored as float2 (x[2m], x[2m+1]) so the
// flat float view is the natural frame layout frames[frame][n].
__device__ float2 g_frames[(size_t)TOTAL_FRAMES * HALF];

__global__ __launch_bounds__(256) void istft_pass1(
    const float* __restrict__ re, const float* __restrict__ im) {
    __shared__ float2 sX[NBINS];   // 513 entries; doubles as ping-pong buffer
    __shared__ float2 sA[HALF];
    __shared__ float2 sW[256];     // W[r] = cis(+2*pi*r/512)

    const int t = threadIdx.x;          // 0..255
    const int frame = blockIdx.x;       // 0..32767
    const float* rp = re + (size_t)frame * NBINS;
    const float* ip = im + (size_t)frame * NBINS;

    // Load spectrum. c2r semantics: imag parts of DC and Nyquist are ignored.
    {
        float r0 = rp[t],       i0 = ip[t];
        float r1 = rp[t + 256], i1 = ip[t + 256];
        if (t == 0) i0 = 0.0f;                       // DC imag dropped
        sX[t]       = make_float2(r0, i0);
        sX[t + 256] = make_float2(r1, i1);
        if (t == 0) sX[512] = make_float2(rp[512], 0.0f);  // Nyquist imag dropped
    }
    // Twiddle table
    {
        float s, c;
        __sincosf((float)t * (6.2831853071795864f / 512.0f), &s, &c);
        sW[t] = make_float2(c, s);
    }
    __syncthreads();

    // Build Z[k] for k = t and k = t+256.
    // Z[k] = E + i*O, E = (X[k]+conj(X[512-k]))/2,
    //                 O = cis(2*pi*k/1024) * (X[k]-conj(X[512-k]))/2
    // cis for k=t+256 is i*cis(k=t) = (-st, ct): one sincos covers both.
    {
        float st, ct;
        __sincosf((float)t * (6.2831853071795864f / 1024.0f), &st, &ct);

        // k = t
        float2 Xa = sX[t];
        float2 Xb = sX[512 - t];
        float Ex = 0.5f * (Xa.x + Xb.x), Ey = 0.5f * (Xa.y - Xb.y);
        float Dx = 0.5f * (Xa.x - Xb.x), Dy = 0.5f * (Xa.y + Xb.y);
        float Ox = ct * Dx - st * Dy;
        float Oy = ct * Dy + st * Dx;
        float2 z0 = make_float2(Ex - Oy, Ey + Ox);

        // k = t + 256, twiddle = (-st, ct)
        float2 Xc = sX[t + 256];
        float2 Xd = sX[256 - t];
        float Ex2 = 0.5f * (Xc.x + Xd.x), Ey2 = 0.5f * (Xc.y - Xd.y);
        float Dx2 = 0.5f * (Xc.x - Xd.x), Dy2 = 0.5f * (Xc.y + Xd.y);
        float Ox2 = -st * Dx2 - ct * Dy2;
        float Oy2 = -st * Dy2 + ct * Dx2;
        float2 z1 = make_float2(Ex2 - Oy2, Ey2 + Ox2);

        sA[t]       = z0;
        sA[t + 256] = z1;
    }
    // Single barrier: orders (a) all sX reads above vs stage-0 sX writes below,
    // and (b) sA writes vs stage-0 sA reads.
    __syncthreads();

    // 9-stage radix-2 Stockham inverse FFT (unnormalized, sign +1).
    float2* src = sA;
    float2* dst = sX;
    #pragma unroll
    for (int stage = 0; stage < 9; ++stage) {
        const int Ns = 1 << stage;
        const int p  = t & (Ns - 1);
        float2 w = sW[p << (8 - stage)];      // cis(2*pi*p/(2*Ns))
        float2 a = src[t];
        float2 b = src[t + 256];
        float btx = b.x * w.x - b.y * w.y;
        float bty = b.x * w.y + b.y * w.x;
        int idxD = ((t - p) << 1) + p;        // (j/Ns)*2Ns + (j%Ns)
        dst[idxD]      = make_float2(a.x + btx, a.y + bty);
        dst[idxD + Ns] = make_float2(a.x - btx, a.y - bty);
        __syncthreads();
        float2* tmp = src; src = dst; dst = tmp;
    }
    // Result (9 stages, odd) is in sX == src.

    // Window * hann(n) / (1.5 * 512) and store.
    float2* out = g_frames + (size_t)frame * HALF;
    #pragma unroll
    for (int h = 0; h < 2; ++h) {
        int m = t + h * 256;
        float2 u = src[m];
        float c0 = __cosf((float)(2 * m)     * (6.2831853071795864f / 1024.0f));
        float c1 = __cosf((float)(2 * m + 1) * (6.2831853071795864f / 1024.0f));
        float w0 = (0.5f - 0.5f * c0) * (1.0f / 768.0f);
        float w1 = (0.5f - 0.5f * c1) * (1.0f / 768.0f);
        out[m] = make_float2(u.x * w0, u.y * w1);
    }
}

__global__ __launch_bounds__(256) void istft_pass2(float* __restrict__ out) {
    const int p  = blockIdx.x * 256 + threadIdx.x;   // 0..130815
    const int b  = blockIdx.y;
    const int pg = p + 512;                          // untrimmed position
    const int fh = pg >> 8;                          // highest contributing frame
    const float* base = (const float*)g_frames + (size_t)b * NFRAMES * N_FFT;

    float acc = 0.0f;
    #pragma unroll
    for (int j = 0; j < 4; ++j) {
        int f = fh - j;
        if (f >= 0 && f < NFRAMES) {
            acc += base[f * N_FFT + (pg - (f << 8))];
        }
    }
    out[(size_t)b * OUT_PER_B + p] = acc;
}

extern "C" void kernel_launch(void* const* d_in, const int* in_sizes, int n_in,
                              void* d_out, int out_size) {
    const float* re = (const float*)d_in[0];
    const float* im = (const float*)d_in[1];
    istft_pass1<<<TOTAL_FRAMES, 256>>>(re, im);
    dim3 g2(OUT_PER_B / 256, NB);
    istft_pass2<<<g2, 256>>>((float*)d_out);
}

// round 3
// speedup vs baseline: 1.6196x; 1.6196x over previous
#include <cuda_runtime.h>

#define N_FFT   1024
#define HALF    512
#define NBINS   513
#define NB      64
#define NFRAMES 512
#define HOP     256
#define OUT_PER_B 130816           // 511*256
#define TOTAL_FRAMES (NB * NFRAMES)

// Windowed irfft frames; float4 = (x[4t],x[4t+1],x[4t+2],x[4t+3]) per thread t.
__device__ float4 g_frames4[(size_t)TOTAL_FRAMES * 256];

// Precomputed tables (filled by init kernel every launch; deterministic).
__device__ float2 d_twid[256];   // cis(+2*pi*r/512)
__device__ float2 d_ztw[256];    // cis(+2*pi*k/1024)
__device__ float  d_win[1024];   // hann(n) / (1.5 * 512)

__device__ __forceinline__ float2 cmul(float2 a, float2 b) {
    return make_float2(a.x * b.x - a.y * b.y, a.x * b.y + a.y * b.x);
}
__device__ __forceinline__ int swz(int i) { return i ^ ((i >> 4) & 15); }

__global__ void init_tables() {
    int t = threadIdx.x;  // 256 threads
    float s, c;
    sincosf((float)t * (6.283185307179586f / 512.0f), &s, &c);
    d_twid[t] = make_float2(c, s);
    sincosf((float)t * (6.283185307179586f / 1024.0f), &s, &c);
    d_ztw[t] = make_float2(c, s);
    #pragma unroll
    for (int n = t; n < 1024; n += 256) {
        float cw = cosf((float)n * (6.283185307179586f / 1024.0f));
        d_win[n] = (0.5f - 0.5f * cw) * (1.0f / 768.0f);
    }
}

__global__ __launch_bounds__(256) void istft_pass1(
    const float* __restrict__ re, const float* __restrict__ im) {
    __shared__ __align__(16) float2 sX[514];   // spectrum; reused as float4 bufB
    __shared__ __align__(16) float2 sZ[512];   // swizzled Z; reused as float4 bufA
    __shared__ float2 sW[256];                 // swizzled twiddles

    const int t = threadIdx.x;
    const int frame = blockIdx.x;
    const float* rp = re + (size_t)frame * NBINS;
    const float* ip = im + (size_t)frame * NBINS;

    // Load spectrum (c2r semantics: imag of DC and Nyquist dropped).
    {
        float r0 = rp[t],       i0 = ip[t];
        float r1 = rp[t + 256], i1 = ip[t + 256];
        if (t == 0) i0 = 0.0f;
        sX[t]       = make_float2(r0, i0);
        sX[t + 256] = make_float2(r1, i1);
        if (t == 0) sX[512] = make_float2(rp[512], 0.0f);
        sW[swz(t)] = d_twid[t];
    }
    __syncthreads();  // B1

    // Build Z[k] for k=t, k=t+256 (pack for complex ifft-512), store swizzled.
    {
        float2 wz = d_ztw[t];
        float ct = wz.x, st = wz.y;

        float2 Xa = sX[t];
        float2 Xb = sX[512 - t];
        float Ex = 0.5f * (Xa.x + Xb.x), Ey = 0.5f * (Xa.y - Xb.y);
        float Dx = 0.5f * (Xa.x - Xb.x), Dy = 0.5f * (Xa.y + Xb.y);
        float Ox = ct * Dx - st * Dy;
        float Oy = ct * Dy + st * Dx;
        float2 z0 = make_float2(Ex - Oy, Ey + Ox);

        float2 Xc = sX[t + 256];
        float2 Xd = sX[256 - t];
        float Ex2 = 0.5f * (Xc.x + Xd.x), Ey2 = 0.5f * (Xc.y - Xd.y);
        float Dx2 = 0.5f * (Xc.x - Xd.x), Dy2 = 0.5f * (Xc.y + Xd.y);
        float Ox2 = -st * Dx2 - ct * Dy2;
        float Oy2 = -st * Dy2 + ct * Dx2;
        float2 z1 = make_float2(Ex2 - Oy2, Ey2 + Ox2);

        sZ[swz(t)]       = z0;
        sZ[swz(t + 256)] = z1;
    }
    __syncthreads();  // B2

    // Gather bit-reversed input: thread t holds elements a[2t], a[2t+1],
    // where a[e] = Z[bitrev9(e)]; a[2t] = Z[br8(t)], a[2t+1] = Z[br8(t)+256].
    const int r = __brev((unsigned)t) >> 24;
    float2 v0 = sZ[swz(r)];
    float2 v1 = sZ[swz(r + 256)];

    // Stage d=1 (in-thread, w=1)
    {
        float2 u = make_float2(v0.x + v1.x, v0.y + v1.y);
        v1 = make_float2(v0.x - v1.x, v0.y - v1.y);
        v0 = u;
    }

    // Stages d=2..32 via warp shuffles (thread mask m = d/2).
    #pragma unroll
    for (int s = 1; s <= 5; ++s) {
        const int m = 1 << (s - 1);        // thread xor mask
        const int dm1 = (m << 1) - 1;      // d-1
        const bool up = (t & m) != 0;
        const int j0 = (2 * t) & dm1;
        float2 w0 = sW[swz(j0 << (8 - s))];
        float2 w1 = sW[swz((j0 + 1) << (8 - s))];
        float2 o0, o1;
        o0.x = __shfl_xor_sync(0xffffffffu, v0.x, m);
        o0.y = __shfl_xor_sync(0xffffffffu, v0.y, m);
        o1.x = __shfl_xor_sync(0xffffffffu, v1.x, m);
        o1.y = __shfl_xor_sync(0xffffffffu, v1.y, m);
        float2 U0 = up ? v0 : o0, L0 = up ? o0 : v0;
        float2 U1 = up ? v1 : o1, L1 = up ? o1 : v1;
        float2 wu0 = cmul(w0, U0);
        float2 wu1 = cmul(w1, U1);
        v0 = up ? make_float2(L0.x - wu0.x, L0.y - wu0.y)
                : make_float2(L0.x + wu0.x, L0.y + wu0.y);
        v1 = up ? make_float2(L1.x - wu1.x, L1.y - wu1.y)
                : make_float2(L1.x + wu1.x, L1.y + wu1.y);
    }

    // Stages d=64,128,256 via shared memory (float4 ping-pong, conflict-free).
    float4* bufA = (float4*)sZ;
    float4* bufB = (float4*)sX;
    __syncthreads();  // B3: all gather reads of sZ done before overwrite
    #pragma unroll
    for (int s = 6; s <= 8; ++s) {
        const int m = 1 << (s - 1);        // thread xor mask = d/2
        const int dm1 = (m << 1) - 1;
        const bool up = (t & m) != 0;
        float4* buf = (s == 7) ? bufB : bufA;  // ping-pong avoids WAR barriers
        buf[t] = make_float4(v0.x, v0.y, v1.x, v1.y);
        __syncthreads();  // B4/B5/B6
        float4 q = buf[t ^ m];
        float2 o0 = make_float2(q.x, q.y);
        float2 o1 = make_float2(q.z, q.w);
        const int j0 = (2 * t) & dm1;
        float2 w0 = sW[swz(j0 << (8 - s))];
        float2 w1 = sW[swz((j0 + 1) << (8 - s))];
        float2 U0 = up ? v0 : o0, L0 = up ? o0 : v0;
        float2 U1 = up ? v1 : o1, L1 = up ? o1 : v1;
        float2 wu0 = cmul(w0, U0);
        float2 wu1 = cmul(w1, U1);
        v0 = up ? make_float2(L0.x - wu0.x, L0.y - wu0.y)
                : make_float2(L0.x + wu0.x, L0.y + wu0.y);
        v1 = up ? make_float2(L1.x - wu1.x, L1.y - wu1.y)
                : make_float2(L1.x + wu1.x, L1.y + wu1.y);
    }

    // v0 = y[2t], v1 = y[2t+1]; x[4t..4t+3] = (Re v0, Im v0, Re v1, Im v1).
    float4 w4 = ((const float4*)d_win)[t];
    float4 o;
    o.x = v0.x * w4.x;
    o.y = v0.y * w4.y;
    o.z = v1.x * w4.z;
    o.w = v1.y * w4.w;
    g_frames4[(size_t)frame * 256 + t] = o;
}

__global__ __launch_bounds__(256) void istft_pass2(float* __restrict__ out) {
    const int idx = blockIdx.x * 256 + threadIdx.x;
    const int p4 = idx * 4;                 // output float index (trimmed)
    if (p4 >= OUT_PER_B) return;
    const int b = blockIdx.y;
    const int pg = p4 + 512;                // untrimmed position
    const int fh = pg >> 8;                 // highest contributing frame
    const float* base = (const float*)g_frames4 + (size_t)b * NFRAMES * N_FFT;

    float4 acc = make_float4(0.f, 0.f, 0.f, 0.f);
    #pragma unroll
    for (int j = 0; j < 4; ++j) {
        int f = fh - j;
        if (f >= 0 && f < NFRAMES) {
            const float4 q = *(const float4*)(base + f * N_FFT + (pg - (f << 8)));
            acc.x += q.x; acc.y += q.y; acc.z += q.z; acc.w += q.w;
        }
    }
    *(float4*)(out + (size_t)b * OUT_PER_B + p4) = acc;
}

extern "C" void kernel_launch(void* const* d_in, const int* in_sizes, int n_in,
                              void* d_out, int out_size) {
    const float* re = (const float*)d_in[0];
    const float* im = (const float*)d_in[1];
    init_tables<<<1, 256>>>();
    istft_pass1<<<TOTAL_FRAMES, 256>>>(re, im);
    dim3 g2((OUT_PER_B / 4 + 255) / 256, NB);
    istft_pass2<<<g2, 256>>>((float*)d_out);
}

// round 5
// speedup vs baseline: 1.8946x; 1.1698x over previous
#include <cuda_runtime.h>
#include <cuda_fp16.h>

#define NBINS   513
#define NB      64
#define NFRAMES 512
#define OUT_PER_B 130816           // 511*256
#define TOTAL_FRAMES (NB * NFRAMES)

// ---------------- compile-time tables (no init kernel) ----------------
struct alignas(16) Tabs {
    float2 tw[256];    // cis(+2*pi*r/512)
    float2 ztw[256];   // cis(+2*pi*k/1024)
    float  win[1024];  // hann(n) / (1.5 * 512)
};

constexpr double KPI = 3.141592653589793238462643383279502884;

constexpr double ksin(double x) {          // |x| <= pi, Taylor
    double x2 = x * x, t = x, s = x;
    for (int i = 1; i <= 13; ++i) { t *= -x2 / double((2 * i) * (2 * i + 1)); s += t; }
    return s;
}
constexpr double kcos(double x) {          // |x| <= pi
    double y = KPI * 0.5 - x;              // in [-pi/2, 3pi/2]
    if (y > KPI) y -= 2.0 * KPI;
    return ksin(y);
}
constexpr Tabs mk_tabs() {
    Tabs T{};
    for (int r = 0; r < 256; ++r) {
        double a = 2.0 * KPI * r / 512.0;      // < pi
        T.tw[r]  = { (float)kcos(a), (float)ksin(a) };
        double b = 2.0 * KPI * r / 1024.0;     // < pi
        T.ztw[r] = { (float)kcos(b), (float)ksin(b) };
    }
    for (int n = 0; n < 1024; ++n) {
        double a = 2.0 * KPI * n / 1024.0;
        if (a > KPI) a -= 2.0 * KPI;
        T.win[n] = (float)((0.5 - 0.5 * kcos(a)) / 768.0);
    }
    return T;
}
__device__ const Tabs TAB = mk_tabs();

// fp16 scratch: per frame 256 uint2, each = 4 consecutive windowed samples.
__device__ uint2 g_h[(size_t)TOTAL_FRAMES * 256];

__device__ __forceinline__ float2 cmul(float2 a, float2 b) {
    return make_float2(a.x * b.x - a.y * b.y, a.x * b.y + a.y * b.x);
}
__device__ __forceinline__ int swz(int i) { return i ^ ((i >> 4) & 15); }

__global__ __launch_bounds__(256) void istft_pass1(
    const float* __restrict__ re, const float* __restrict__ im) {
    __shared__ __align__(16) float2 sX[514];   // spectrum; reused as float4 bufB
    __shared__ __align__(16) float2 sZ[512];   // swizzled Z; reused as float4 bufA
    __shared__ float2 sW[256];                 // swizzled twiddles cis(2pi r/512)

    const int t = threadIdx.x;
    const int frame = blockIdx.x;
    const float* rp = re + (size_t)frame * NBINS;
    const float* ip = im + (size_t)frame * NBINS;

    // Load spectrum (c2r semantics: imag of DC and Nyquist dropped).
    {
        float r0 = rp[t],       i0 = ip[t];
        float r1 = rp[t + 256], i1 = ip[t + 256];
        if (t == 0) i0 = 0.0f;
        sX[t]       = make_float2(r0, i0);
        sX[t + 256] = make_float2(r1, i1);
        if (t == 0) sX[512] = make_float2(rp[512], 0.0f);
        sW[swz(t)] = TAB.tw[t];
    }
    __syncthreads();  // B1

    // Pack Z[k] for complex ifft-512; store swizzled.
    {
        float2 wz = TAB.ztw[t];
        float ct = wz.x, st = wz.y;

        float2 Xa = sX[t];
        float2 Xb = sX[512 - t];
        float Ex = 0.5f * (Xa.x + Xb.x), Ey = 0.5f * (Xa.y - Xb.y);
        float Dx = 0.5f * (Xa.x - Xb.x), Dy = 0.5f * (Xa.y + Xb.y);
        float Ox = ct * Dx - st * Dy;
        float Oy = ct * Dy + st * Dx;
        float2 z0 = make_float2(Ex - Oy, Ey + Ox);

        float2 Xc = sX[t + 256];
        float2 Xd = sX[256 - t];
        float Ex2 = 0.5f * (Xc.x + Xd.x), Ey2 = 0.5f * (Xc.y - Xd.y);
        float Dx2 = 0.5f * (Xc.x - Xd.x), Dy2 = 0.5f * (Xc.y + Xd.y);
        float Ox2 = -st * Dx2 - ct * Dy2;
        float Oy2 = -st * Dy2 + ct * Dx2;
        float2 z1 = make_float2(Ex2 - Oy2, Ey2 + Ox2);

        sZ[swz(t)]       = z0;
        sZ[swz(t + 256)] = z1;
    }
    __syncthreads();  // B2

    // Bit-reversed gather: a[2t] = Z[br8(t)], a[2t+1] = Z[br8(t)+256].
    const int r = __brev((unsigned)t) >> 24;
    float2 v0 = sZ[swz(r)];
    float2 v1 = sZ[swz(r + 256)];

    // Stage d=1 (in-thread, w=1).
    {
        float2 u = make_float2(v0.x + v1.x, v0.y + v1.y);
        v1 = make_float2(v0.x - v1.x, v0.y - v1.y);
        v0 = u;
    }

    // Stages d=2..32 via warp shuffles. Pre-twiddle exchange:
    //   p = self * w_lane (low lanes w=(1,0) via masked index),
    //   out = exchange(p) + sgn * p, sgn = up ? -1 : +1.
    #pragma unroll
    for (int s = 1; s <= 5; ++s) {
        const int m = 1 << (s - 1);             // thread xor mask = d/2
        const bool up = (t & m) != 0;
        const float sgn = up ? -1.0f : 1.0f;
        const int jm = up ? ((m << 1) - 1) : 0; // d-1 for v-side, 0 for u-side
        const int sh = 8 - s;
        float2 w0 = sW[swz(((2 * t) & jm) << sh)];
        float2 w1 = sW[swz(((2 * t + 1) & jm) << sh)];
        float2 p0 = cmul(v0, w0);
        float2 p1 = cmul(v1, w1);
        float2 e0, e1;
        e0.x = __shfl_xor_sync(0xffffffffu, p0.x, m);
        e0.y = __shfl_xor_sync(0xffffffffu, p0.y, m);
        e1.x = __shfl_xor_sync(0xffffffffu, p1.x, m);
        e1.y = __shfl_xor_sync(0xffffffffu, p1.y, m);
        v0 = make_float2(fmaf(sgn, p0.x, e0.x), fmaf(sgn, p0.y, e0.y));
        v1 = make_float2(fmaf(sgn, p1.x, e1.x), fmaf(sgn, p1.y, e1.y));
    }

    // Stages d=64,128,256 via shared memory (float4 ping-pong, conflict-free).
    float4* bufA = (float4*)sZ;
    float4* bufB = (float4*)sX;
    __syncthreads();  // B3: gather reads of sZ done before overwrite
    #pragma unroll
    for (int s = 6; s <= 8; ++s) {
        const int m = 1 << (s - 1);
        const bool up = (t & m) != 0;
        const float sgn = up ? -1.0f : 1.0f;
        const int jm = up ? ((m << 1) - 1) : 0;
        const int sh = 8 - s;
        float2 w0 = sW[swz(((2 * t) & jm) << sh)];
        float2 w1 = sW[swz(((2 * t + 1) & jm) << sh)];
        float2 p0 = cmul(v0, w0);
        float2 p1 = cmul(v1, w1);
        float4* buf = (s == 7) ? bufB : bufA;
        buf[t] = make_float4(p0.x, p0.y, p1.x, p1.y);
        __syncthreads();  // B4/B5/B6
        float4 q = buf[t ^ m];
        v0 = make_float2(fmaf(sgn, p0.x, q.x), fmaf(sgn, p0.y, q.y));
        v1 = make_float2(fmaf(sgn, p1.x, q.z), fmaf(sgn, p1.y, q.w));
    }

    // v0 = y[2t], v1 = y[2t+1] -> x[4t..4t+3]; window, fp16 pack, store.
    float4 w4 = ((const float4*)TAB.win)[t];
    __half2 h01 = __floats2half2_rn(v0.x * w4.x, v0.y * w4.y);
    __half2 h23 = __floats2half2_rn(v1.x * w4.z, v1.y * w4.w);
    uint2 o;
    o.x = *reinterpret_cast<unsigned*>(&h01);
    o.y = *reinterpret_cast<unsigned*>(&h23);
    g_h[(size_t)frame * 256 + t] = o;
}

__global__ __launch_bounds__(256) void istft_pass2(float* __restrict__ out) {
    const int idx = blockIdx.x * 256 + threadIdx.x;
    const int p4 = idx * 4;                 // trimmed output float index
    if (p4 >= OUT_PER_B) return;
    const int b = blockIdx.y;
    const int pg = p4 + 512;                // untrimmed position
    const int fh = pg >> 8;                 // highest contributing frame
    const uint2* base = g_h + (size_t)b * NFRAMES * 256;

    float4 acc = make_float4(0.f, 0.f, 0.f, 0.f);
    #pragma unroll
    for (int j = 0; j < 4; ++j) {
        int f = fh - j;
        if (f >= 0 && f < NFRAMES) {
            uint2 q = base[f * 256 + ((pg - (f << 8)) >> 2)];
            __half2 a = *reinterpret_cast<__half2*>(&q.x);
            __half2 c = *reinterpret_cast<__half2*>(&q.y);
            float2 fa = __half22float2(a);
            float2 fc = __half22float2(c);
            acc.x += fa.x; acc.y += fa.y; acc.z += fc.x; acc.w += fc.y;
        }
    }
    *(float4*)(out + (size_t)b * OUT_PER_B + p4) = acc;
}

extern "C" void kernel_launch(void* const* d_in, const int* in_sizes, int n_in,
                              void* d_out, int out_size) {
    const float* re = (const float*)d_in[0];
    const float* im = (const float*)d_in[1];
    istft_pass1<<<TOTAL_FRAMES, 256>>>(re, im);
    dim3 g2((OUT_PER_B / 4 + 255) / 256, NB);
    istft_pass2<<<g2, 256>>>((float*)d_out);
}

// round 6
// speedup vs baseline: 1.9240x; 1.0155x over previous
#include <cuda_runtime.h>
#include <cuda_fp16.h>

#define NBINS   513
#define NB      64
#define NFRAMES 512
#define OUT_PER_B 130816           // 511*256
#define TOTAL_FRAMES (NB * NFRAMES)

// ---------------- compile-time tables ----------------
struct alignas(16) Tabs {
    float2 tw[512];    // cis(+2*pi*r/512)
    float2 ztw[512];   // cis(+2*pi*k/1024)
    float  win[1024];  // hann(n) / (1.5 * 512)
};

constexpr double KPI = 3.141592653589793238462643383279502884;

constexpr double ksin(double x) {          // |x| <= pi, Taylor
    double x2 = x * x, t = x, s = x;
    for (int i = 1; i <= 13; ++i) { t *= -x2 / double((2 * i) * (2 * i + 1)); s += t; }
    return s;
}
constexpr double kcos(double x) {          // |x| <= pi
    double y = KPI * 0.5 - x;              // in [-pi/2, 3pi/2]
    if (y > KPI) y -= 2.0 * KPI;
    return ksin(y);
}
constexpr float2 kcis(double a) {          // a in [0, 2pi)
    if (a > KPI) a -= 2.0 * KPI;
    return { (float)kcos(a), (float)ksin(a) };
}
constexpr Tabs mk_tabs() {
    Tabs T{};
    for (int r = 0; r < 512; ++r) {
        T.tw[r]  = kcis(2.0 * KPI * r / 512.0);
        T.ztw[r] = kcis(2.0 * KPI * r / 1024.0);
    }
    for (int n = 0; n < 1024; ++n) {
        double a = 2.0 * KPI * n / 1024.0;
        if (a > KPI) a -= 2.0 * KPI;
        T.win[n] = (float)((0.5 - 0.5 * kcos(a)) / 768.0);
    }
    return T;
}
__device__ const Tabs TAB = mk_tabs();

// fp16 scratch frames: uint holds half2 = samples (2m, 2m+1).
__device__ uint4 g_h4[(size_t)TOTAL_FRAMES * 128];

__device__ __forceinline__ float2 cmul(float2 a, float2 b) {
    return make_float2(a.x * b.x - a.y * b.y, a.x * b.y + a.y * b.x);
}
// inverse DFT4: y_n = sum_r x_r * i^(n*r)
__device__ __forceinline__ void idft4(float2 a, float2 b, float2 c, float2 d,
                                      float2& y0, float2& y1, float2& y2, float2& y3) {
    float2 s0 = make_float2(a.x + c.x, a.y + c.y);
    float2 d0 = make_float2(a.x - c.x, a.y - c.y);
    float2 s1 = make_float2(b.x + d.x, b.y + d.y);
    float2 d1 = make_float2(b.x - d.x, b.y - d.y);
    y0 = make_float2(s0.x + s1.x, s0.y + s1.y);
    y1 = make_float2(d0.x - d1.y, d0.y + d1.x);   // d0 + i*d1
    y2 = make_float2(s0.x - s1.x, s0.y - s1.y);
    y3 = make_float2(d0.x + d1.y, d0.y - d1.x);   // d0 - i*d1
}

__global__ __launch_bounds__(128) void istft_pass1(
    const float* __restrict__ re, const float* __restrict__ im) {
    const int lane  = threadIdx.x & 31;
    const int frame = blockIdx.x * 4 + (threadIdx.x >> 5);
    const float* rp = re + (size_t)frame * NBINS;
    const float* ip = im + (size_t)frame * NBINS;

    // ---- Load + rfft->complex pack: Z[k2] for k = lane + 32*k2 ----
    // Z[k] = E + i*O; E=(X[k]+conj(X[512-k]))/2, O=cis(2pi k/1024)*(X[k]-conj(X[512-k]))/2
    float2 z[16];
    #pragma unroll
    for (int k2 = 0; k2 < 16; ++k2) {
        const int k = lane + 32 * k2;
        float xar = __ldg(rp + k),       xai = __ldg(ip + k);
        float xbr = __ldg(rp + 512 - k), xbi = __ldg(ip + 512 - k);
        if (k == 0) { xai = 0.0f; xbi = 0.0f; }   // c2r drops imag(DC), imag(Nyquist)
        float2 wz = TAB.ztw[k];
        float Ex = 0.5f * (xar + xbr), Ey = 0.5f * (xai - xbi);
        float Dx = 0.5f * (xar - xbr), Dy = 0.5f * (xai + xbi);
        float Ox = wz.x * Dx - wz.y * Dy;
        float Oy = wz.x * Dy + wz.y * Dx;
        z[k2] = make_float2(Ex - Oy, Ey + Ox);
    }

    // ---- 16-pt inverse DFT over k2 in registers (constant twiddles) ----
    // k2 = k2a + 4*k2b ; n2 = n2b + 4*n2a
    float2 G[16];   // G[k2a*4 + n2b]
    #pragma unroll
    for (int g = 0; g < 4; ++g)
        idft4(z[g], z[g + 4], z[g + 8], z[g + 12],
              G[g * 4 + 0], G[g * 4 + 1], G[g * 4 + 2], G[g * 4 + 3]);

    // G[g][n] *= cis(2*pi*g*n/16)
    {
        const float2 w1 = { 0.92387953251f,  0.38268343236f };
        const float2 w2 = { 0.70710678119f,  0.70710678119f };
        const float2 w3 = { 0.38268343236f,  0.92387953251f };
        const float2 w6 = {-0.70710678119f,  0.70710678119f };
        const float2 w9 = {-0.92387953251f, -0.38268343236f };
        G[5]  = cmul(G[5],  w1);                        // (1,1)
        G[6]  = cmul(G[6],  w2);                        // (1,2)
        G[7]  = cmul(G[7],  w3);                        // (1,3)
        G[9]  = cmul(G[9],  w2);                        // (2,1)
        G[10] = make_float2(-G[10].y, G[10].x);         // (2,2): *i
        G[11] = cmul(G[11], w6);                        // (2,3)
        G[13] = cmul(G[13], w3);                        // (3,1)
        G[14] = cmul(G[14], w6);                        // (3,2)
        G[15] = cmul(G[15], w9);                        // (3,3)
    }

    float2 B[16];   // B[n2]
    #pragma unroll
    for (int n2b = 0; n2b < 4; ++n2b)
        idft4(G[0 * 4 + n2b], G[1 * 4 + n2b], G[2 * 4 + n2b], G[3 * 4 + n2b],
              B[n2b + 0], B[n2b + 4], B[n2b + 8], B[n2b + 12]);

    // ---- per-lane twiddle: B[n2] *= cis(2*pi*n2*lane/512) ----
    #pragma unroll
    for (int n2 = 1; n2 < 16; ++n2)
        B[n2] = cmul(B[n2], TAB.tw[n2 * lane]);

    // ---- 32-pt inverse DFT across lanes: 5 DIF shuffle stages ----
    // pair (L, L^m): out = w_eff * (exch + s*self); lower: s=+1,w=1; upper: s=-1,
    // w = cis(2*pi*(L&(m-1))/(2m)).
    #pragma unroll
    for (int st = 0; st < 4; ++st) {
        const int m = 16 >> st;
        const bool up = (lane & m) != 0;
        const float s = up ? -1.0f : 1.0f;
        const float2 w = TAB.tw[up ? (lane & (m - 1)) * (256 / m) : 0];
        #pragma unroll
        for (int n2 = 0; n2 < 16; ++n2) {
            float ex = __shfl_xor_sync(0xffffffffu, B[n2].x, m);
            float ey = __shfl_xor_sync(0xffffffffu, B[n2].y, m);
            float tx = fmaf(s, B[n2].x, ex);
            float ty = fmaf(s, B[n2].y, ey);
            B[n2] = make_float2(w.x * tx - w.y * ty, w.x * ty + w.y * tx);
        }
    }
    {   // last stage m=1: w == 1 for all lanes
        const float s = (lane & 1) ? -1.0f : 1.0f;
        #pragma unroll
        for (int n2 = 0; n2 < 16; ++n2) {
            float ex = __shfl_xor_sync(0xffffffffu, B[n2].x, 1);
            float ey = __shfl_xor_sync(0xffffffffu, B[n2].y, 1);
            B[n2] = make_float2(fmaf(s, B[n2].x, ex), fmaf(s, B[n2].y, ey));
        }
    }

    // Lane L holds y[n2 + 16*R], R = bitrev5(L).
    // x[2m] = Re y[m], x[2m+1] = Im y[m] -> thread owns samples [32R, 32R+32).
    const int R = (int)(__brev((unsigned)lane) >> 27);
    const float4* w4p = (const float4*)TAB.win + 8 * R;
    unsigned us[16];
    #pragma unroll
    for (int j = 0; j < 8; ++j) {
        float4 wv = w4p[j];
        float2 y0 = B[2 * j], y1 = B[2 * j + 1];
        __half2 h0 = __floats2half2_rn(y0.x * wv.x, y0.y * wv.y);
        __half2 h1 = __floats2half2_rn(y1.x * wv.z, y1.y * wv.w);
        us[2 * j]     = *reinterpret_cast<unsigned*>(&h0);
        us[2 * j + 1] = *reinterpret_cast<unsigned*>(&h1);
    }
    uint4* dst = (uint4*)((unsigned*)g_h4 + (size_t)frame * 512 + 16 * R);
    dst[0] = make_uint4(us[0],  us[1],  us[2],  us[3]);
    dst[1] = make_uint4(us[4],  us[5],  us[6],  us[7]);
    dst[2] = make_uint4(us[8],  us[9],  us[10], us[11]);
    dst[3] = make_uint4(us[12], us[13], us[14], us[15]);
}

__global__ __launch_bounds__(256) void istft_pass2(float* __restrict__ out) {
    const int idx = blockIdx.x * 256 + threadIdx.x;
    const int p4 = idx * 4;                 // trimmed output float index
    if (p4 >= OUT_PER_B) return;
    const int b = blockIdx.y;
    const int pg = p4 + 512;                // untrimmed position
    const int fh = pg >> 8;                 // highest contributing frame
    const uint2* base = (const uint2*)g_h4 + (size_t)b * NFRAMES * 256;

    float4 acc = make_float4(0.f, 0.f, 0.f, 0.f);
    #pragma unroll
    for (int j = 0; j < 4; ++j) {
        int f = fh - j;
        if (f >= 0 && f < NFRAMES) {
            uint2 q = base[f * 256 + ((pg - (f << 8)) >> 2)];
            __half2 a = *reinterpret_cast<__half2*>(&q.x);
            __half2 c = *reinterpret_cast<__half2*>(&q.y);
            float2 fa = __half22float2(a);
            float2 fc = __half22float2(c);
            acc.x += fa.x; acc.y += fa.y; acc.z += fc.x; acc.w += fc.y;
        }
    }
    *(float4*)(out + (size_t)b * OUT_PER_B + p4) = acc;
}

extern "C" void kernel_launch(void* const* d_in, const int* in_sizes, int n_in,
                              void* d_out, int out_size) {
    const float* re = (const float*)d_in[0];
    const float* im = (const float*)d_in[1];
    istft_pass1<<<TOTAL_FRAMES / 4, 128>>>(re, im);
    dim3 g2((OUT_PER_B / 4 + 255) / 256, NB);
    istft_pass2<<<g2, 256>>>((float*)d_out);
}